// round 16
// baseline (speedup 1.0000x reference)
#include <cuda_runtime.h>
#include <math.h>
#include <stdint.h>

#define BB 32
#define NPB 2048
#define NN 65536
#define EE 1048576
#define HH 768
#define NH 8
#define DHH 96
#define KC 48
#define SCALE_V 0.10206207261596577f

// ---------------- unified fp32 scratch (zeroed once per launch) ----------------
#define O_QP     0
#define O_Q      24576
#define O_QP2    49152
#define O_T      73728
#define O_U      98304
#define O_CTX    294912
#define O_TMP1   319488
#define O_BMEAN  344064
#define O_AGG1   368640
#define O_AGG    393216
#define O_GATE   417792
#define O_FUSED  442368
#define O_WSUM   466944
#define O_MEANX  663552
#define O_MEANP  753664
#define O_PATH   802816
#define O_GRAPH  827392
#define O_COMB   851968
#define O_NUM    925952
#define O_QN     991488
#define O_C      991520
#define TOTALF   991552

__device__ float g_buf[TOTALF];
__device__ float g_scores[(size_t)NN*NH];   // holds exp(score)
__device__ float g_se[BB*NH];
__device__ float g_csimp[BB*KC*3];
__device__ int   g_first_edge[NN];
__device__ int   g_cand[BB*KC];
__device__ int   g_cnt[BB];

// ---------------- prep: zero scratch, init first_edge ----------------
__global__ void k_prep() {
    int i = blockIdx.x * 256 + threadIdx.x;
    if (i < TOTALF) g_buf[i] = 0.f;
    if (i < NN) g_first_edge[i] = EE;
    if (i < BB * NH) g_se[i] = 0.f;
}

// ---------------- multi-descriptor split-K small GEMM ----------------
struct GDesc {
    const float* A; const float* B; const float* bias; float* C;
    int lda, ldb, ldc, transB, K, actA, nx, ky;
};
struct GPack { GDesc d[8]; };

__global__ void k_gskm(GPack p) {
    GDesc d = p.d[blockIdx.z];
    if ((int)blockIdx.x >= d.nx || (int)blockIdx.y >= d.ky) return;
    __shared__ float sA[32][129];
    __shared__ float sB[128][33];
    int t = threadIdx.x;
    int c0 = blockIdx.x * 32, k0 = blockIdx.y * 128;
    int kn = min(128, d.K - k0);
    for (int idx = t; idx < 32 * 128; idx += 256) {
        int m = idx >> 7, kk = idx & 127;
        float v = (kk < kn) ? d.A[(size_t)m * d.lda + k0 + kk] : 0.f;
        if (d.actA) v = fmaxf(v, 0.f);
        sA[m][kk] = v;
    }
    for (int idx = t; idx < 128 * 32; idx += 256) {
        int kk = idx >> 5, nn = idx & 31;
        float v = 0.f;
        if (kk < kn) v = d.transB ? d.B[(size_t)(c0 + nn) * d.ldb + k0 + kk]
                                  : d.B[(size_t)(k0 + kk) * d.ldb + c0 + nn];
        sB[kk][nn] = v;
    }
    __syncthreads();
    int g = t >> 5, tx = t & 31;
    float a0 = 0.f, a1 = 0.f, a2 = 0.f, a3 = 0.f;
#pragma unroll 8
    for (int kk = 0; kk < 128; kk++) {
        float bv = sB[kk][tx];
        a0 += sA[g][kk] * bv;
        a1 += sA[g + 8][kk] * bv;
        a2 += sA[g + 16][kk] * bv;
        a3 += sA[g + 24][kk] * bv;
    }
    float bb = (d.bias && blockIdx.y == 0) ? d.bias[c0 + tx] : 0.f;
    atomicAdd(&d.C[(size_t)(g     ) * d.ldc + c0 + tx], a0 + bb);
    atomicAdd(&d.C[(size_t)(g +  8) * d.ldc + c0 + tx], a1 + bb);
    atomicAdd(&d.C[(size_t)(g + 16) * d.ldc + c0 + tx], a2 + bb);
    atomicAdd(&d.C[(size_t)(g + 24) * d.ldc + c0 + tx], a3 + bb);
}

// ---------------- qp2 stats ----------------
__global__ void k_qstats(const float* __restrict__ bn) {
    int b = blockIdx.x, t = threadIdx.x;
    __shared__ float s1[256], s2[256];
    float a = 0.f, d = 0.f;
    for (int j = t; j < HH; j += 256) {
        float v = g_buf[O_QP2 + b * HH + j];
        a += v * v; d += v * bn[j];
    }
    s1[t] = a; s2[t] = d; __syncthreads();
    for (int o = 128; o > 0; o >>= 1) {
        if (t < o) { s1[t] += s1[t + o]; s2[t] += s2[t + o]; }
        __syncthreads();
    }
    if (t == 0) { g_buf[O_QN + b] = fmaxf(sqrtf(s1[0]), 1e-8f); g_buf[O_C + b] = s2[0]; }
}

// ---------------- per-node head exp-scores + cosine numerator + fused exp-sums ----------------
// writes exp(score) to g_scores; accumulates per-(b,h) sum of exps into g_se.
// (scores are tiny: exp without max-subtraction is mathematically identical softmax)
__global__ void k_scores(const float* __restrict__ X) {
    __shared__ float sU[NH * HH];
    __shared__ float sT[HH];
    __shared__ float sred[8][8];
    int b = blockIdx.x >> 4, sub = blockIdx.x & 15;
    for (int i = threadIdx.x; i < NH * HH; i += 256) sU[i] = g_buf[O_U + b * NH * HH + i];
    for (int i = threadIdx.x; i < HH; i += 256) sT[i] = g_buf[O_T + b * HH + i];
    __syncthreads();
    float cb = g_buf[O_C + b];
    int warp = threadIdx.x >> 5, lane = threadIdx.x & 31;
    int nodebase = b * NPB + sub * 128 + warp * 16;
    float esum[8];
#pragma unroll
    for (int h = 0; h < 8; h++) esum[h] = 0.f;
    for (int w = 0; w < 16; w++) {
        int n = nodebase + w;
        const float4* xr = (const float4*)(X + (size_t)n * HH);
        float acc[9];
#pragma unroll
        for (int i = 0; i < 9; i++) acc[i] = 0.f;
#pragma unroll
        for (int cc = 0; cc < 6; cc++) {
            int base = cc * 32 + lane;
            float4 xv = xr[base];
#pragma unroll
            for (int h = 0; h < 8; h++) {
                float4 u = ((const float4*)(sU + h * HH))[base];
                acc[h] += xv.x * u.x + xv.y * u.y + xv.z * u.z + xv.w * u.w;
            }
            float4 tv = ((const float4*)sT)[base];
            acc[8] += xv.x * tv.x + xv.y * tv.y + xv.z * tv.z + xv.w * tv.w;
        }
#pragma unroll
        for (int i = 0; i < 9; i++)
            for (int o = 16; o > 0; o >>= 1)
                acc[i] += __shfl_xor_sync(0xffffffffu, acc[i], o);
        if (lane == 0) {
#pragma unroll
            for (int h = 0; h < 8; h++) {
                float e = expf(acc[h] * SCALE_V);
                g_scores[(size_t)n * NH + h] = e;
                esum[h] += e;
            }
            g_buf[O_NUM + n] = acc[8] + cb;
        }
    }
    if (lane == 0)
#pragma unroll
        for (int h = 0; h < 8; h++) sred[warp][h] = esum[h];
    __syncthreads();
    if (threadIdx.x < 8) {
        float s = 0.f;
#pragma unroll
        for (int wp = 0; wp < 8; wp++) s += sred[wp][threadIdx.x];
        atomicAdd(&g_se[b * NH + threadIdx.x], s);
    }
}

// ---------------- attention-weighted sums + mean(x): float4 per thread ----------------
// grid (BB, 16): each CTA handles one 128-node segment; 192 threads x 4 cols = 768 cols.
__global__ void k_wsum(const float* __restrict__ X) {
    int b = blockIdx.x, seg = blockIdx.y;
    int t = threadIdx.x;                // 192
    __shared__ float sa[128][8];
    __shared__ float sse[8];
    if (t < 8) sse[t] = 1.f / g_se[b * NH + t];
    __syncthreads();
    int n0 = seg * 128;
    for (int idx = t; idx < 128 * 8; idx += 192) {
        int n = idx >> 3, h = idx & 7;
        sa[n][h] = g_scores[(size_t)(b * NPB + n0 + n) * NH + h] * sse[h];
    }
    __syncthreads();
    int col = t * 4;
    float acc[8][4];
#pragma unroll
    for (int h = 0; h < 8; h++)
#pragma unroll
        for (int j = 0; j < 4; j++) acc[h][j] = 0.f;
    float m0 = 0.f, m1 = 0.f, m2 = 0.f, m3 = 0.f;
#pragma unroll 4
    for (int nn = 0; nn < 128; nn++) {
        float4 xv = *(const float4*)(X + (size_t)(b * NPB + n0 + nn) * HH + col);
        m0 += xv.x; m1 += xv.y; m2 += xv.z; m3 += xv.w;
#pragma unroll
        for (int h = 0; h < 8; h++) {
            float a = sa[nn][h];
            acc[h][0] += a * xv.x;
            acc[h][1] += a * xv.y;
            acc[h][2] += a * xv.z;
            acc[h][3] += a * xv.w;
        }
    }
#pragma unroll
    for (int h = 0; h < 8; h++) {
        float* wp = &g_buf[O_WSUM + (size_t)(b * NH + h) * HH + col];
        atomicAdd(wp + 0, acc[h][0]);
        atomicAdd(wp + 1, acc[h][1]);
        atomicAdd(wp + 2, acc[h][2]);
        atomicAdd(wp + 3, acc[h][3]);
    }
    float inv = 1.f / (float)NPB;
    float* mp = &g_buf[O_MEANX + b * HH + col];
    atomicAdd(mp + 0, m0 * inv);
    atomicAdd(mp + 1, m1 * inv);
    atomicAdd(mp + 2, m2 * inv);
    atomicAdd(mp + 3, m3 * inv);
}

// ---------------- first intra-graph outgoing edge ----------------
__global__ void k_edges(const int* __restrict__ ei, const int* __restrict__ bidx) {
    int e = blockIdx.x * blockDim.x + threadIdx.x;
    if (e < EE) {
        int s = ei[e], d = ei[EE + e];
        if (bidx[s] == bidx[d]) atomicMin(&g_first_edge[s], e);
    }
}

// ---------------- top-48 shortlist by exact numerator (norms concentrate ±2.5%) ----------------
__global__ void k_topnum() {
    int b = blockIdx.x, t = threadIdx.x;
    __shared__ float sv[NPB];
    __shared__ float rv[256];
    __shared__ int ri[256];
    for (int i = t; i < NPB; i += 256)
        sv[i] = g_buf[O_NUM + b * NPB + i];
    __syncthreads();
    for (int k = 0; k < KC; k++) {
        float bv = -1e38f; int bi = 0x7fffffff;
        for (int i = t; i < NPB; i += 256) {
            float v = sv[i];
            if (v > bv || (v == bv && i < bi)) { bv = v; bi = i; }
        }
        rv[t] = bv; ri[t] = bi; __syncthreads();
        for (int o = 128; o > 0; o >>= 1) {
            if (t < o) {
                if (rv[t + o] > rv[t] || (rv[t + o] == rv[t] && ri[t + o] < ri[t])) {
                    rv[t] = rv[t + o]; ri[t] = ri[t + o];
                }
            }
            __syncthreads();
        }
        if (t == 0) { g_cand[b * KC + k] = b * NPB + ri[0]; sv[ri[0]] = -1e38f; }
        __syncthreads();
    }
}

// ---------------- exact fp32 norm partials for the 48 candidates ----------------
// grid (32, 3, 6): batch x column-third x candidate-group-of-8. Deterministic.
__global__ void k_recheck48(const float* __restrict__ X, const float* __restrict__ W,
                            const float* __restrict__ bn)
{
    int b = blockIdx.x, third = blockIdx.y, grp = blockIdx.z;
    int t = threadIdx.x;
    int col = third * 256 + t;
    __shared__ float sx[8][HH];
    __shared__ float sr[256];
    for (int i = t; i < 8 * HH; i += 256) {
        int c = i / HH, k = i % HH;
        sx[c][k] = X[(size_t)g_cand[b * KC + grp * 8 + c] * HH + k];
    }
    __syncthreads();
    float v[8];
#pragma unroll
    for (int c = 0; c < 8; c++) v[c] = bn[col];
#pragma unroll 4
    for (int k = 0; k < HH; k++) {
        float w = W[(size_t)k * HH + col];
#pragma unroll
        for (int c = 0; c < 8; c++) v[c] += sx[c][k] * w;
    }
    for (int c = 0; c < 8; c++) {
        sr[t] = v[c] * v[c]; __syncthreads();
        for (int o = 128; o > 0; o >>= 1) {
            if (t < o) sr[t] += sr[t + o];
            __syncthreads();
        }
        if (t == 0) g_csimp[(b * KC + grp * 8 + c) * 3 + third] = sr[0];
        __syncthreads();
    }
}

// ---------------- exact top-3 over 48 candidates + path features ----------------
__global__ void k_pathfeat(const float* __restrict__ X, const int* __restrict__ ei) {
    int b = blockIdx.x, t = threadIdx.x;
    __shared__ int st[3], snb[3], sval[3];
    __shared__ int scnt;
    if (t == 0) {
        float v[KC]; int ix[KC]; bool used[KC];
        float qninv = 1.f / g_buf[O_QN + b];
        for (int j = 0; j < KC; j++) {
            int node = g_cand[b * KC + j];
            float nsq = g_csimp[(b * KC + j) * 3 + 0]
                      + g_csimp[(b * KC + j) * 3 + 1]
                      + g_csimp[(b * KC + j) * 3 + 2];
            float nrm = fmaxf(sqrtf(nsq), 1e-8f);
            v[j] = g_buf[O_NUM + node] * qninv / nrm;
            ix[j] = node;
            used[j] = false;
        }
        int c = 0;
        for (int k = 0; k < 3; k++) {
            int best = -1;
            for (int j = 0; j < KC; j++)
                if (!used[j] && (best < 0 || v[j] > v[best] ||
                                 (v[j] == v[best] && ix[j] < ix[best]))) best = j;
            used[best] = true;
            int node = ix[best];
            int fe = g_first_edge[node];
            int vl = (fe < EE) ? 1 : 0;
            int nbr = ei[EE + (vl ? fe : 0)];
            st[k] = node; snb[k] = nbr; sval[k] = vl; c += vl;
        }
        scnt = c; g_cnt[b] = c;
    }
    __syncthreads();
    float invc = 1.f / fmaxf((float)scnt, 1.f);
    for (int j = t; j < HH; j += 256) {
        float s = 0.f;
        for (int k = 0; k < 3; k++)
            if (sval[k])
                s += (X[(size_t)st[k] * HH + j] + X[(size_t)snb[k] * HH + j]) * 0.5f;
        g_buf[O_MEANP + b * HH + j] = s * invc;
    }
}

// ---------------- comb = [query, graph, path] ----------------
__global__ void k_comb(const float* __restrict__ query) {
    int i = blockIdx.x * 256 + threadIdx.x;
    int b = i / (3 * HH), j = i % (3 * HH);
    float v;
    if (j < HH)          v = query[b * HH + j];
    else if (j < 2 * HH) v = g_buf[O_GRAPH + b * HH + j - HH];
    else                 v = g_buf[O_PATH + b * HH + j - 2 * HH];
    g_buf[O_COMB + i] = v;
}

// ---------------- layernorm; mode 2: in *= sigmoid(in2); mode 3: select in/in2 by g_cnt ----------------
__global__ void k_ln(const float* __restrict__ in, const float* __restrict__ in2, int mode,
                     const float* __restrict__ gg, const float* __restrict__ bb,
                     float* __restrict__ out)
{
    int b = blockIdx.x, t = threadIdx.x;
    __shared__ float sx[HH];
    __shared__ float red[256];
    float s = 0.f;
    for (int j = t; j < HH; j += 256) {
        float v = in[b * HH + j];
        if (mode == 2) v *= 1.f / (1.f + expf(-in2[b * HH + j]));
        else if (mode == 3 && g_cnt[b] <= 0) v = in2[b * HH + j];
        sx[j] = v; s += v;
    }
    red[t] = s; __syncthreads();
    for (int o = 128; o > 0; o >>= 1) { if (t < o) red[t] += red[t + o]; __syncthreads(); }
    float m = red[0] * (1.f / HH); __syncthreads();
    float vs = 0.f;
    for (int j = t; j < HH; j += 256) { float d = sx[j] - m; vs += d * d; }
    red[t] = vs; __syncthreads();
    for (int o = 128; o > 0; o >>= 1) { if (t < o) red[t] += red[t + o]; __syncthreads(); }
    float inv = rsqrtf(red[0] * (1.f / HH) + 1e-5f);
    for (int j = t; j < HH; j += 256)
        out[b * HH + j] = (sx[j] - m) * inv * gg[j] + bb[j];
}

// ---------------- host ----------------
static float* addrf(const void* sym) {
    void* p = nullptr;
    cudaGetSymbolAddress(&p, sym);
    return (float*)p;
}

static GDesc mkdesc(const float* A, int lda, const float* B, int ldb, int transB,
                    const float* bias, float* C, int ldc, int Ncols, int K, int actA) {
    GDesc d;
    d.A = A; d.B = B; d.bias = bias; d.C = C;
    d.lda = lda; d.ldb = ldb; d.ldc = ldc; d.transB = transB;
    d.K = K; d.actA = actA;
    d.nx = (Ncols + 31) / 32; d.ky = (K + 127) / 128;
    return d;
}

extern "C" void kernel_launch(void* const* d_in, const int* in_sizes, int n_in,
                              void* d_out, int out_size)
{
    const float* query   = (const float*)d_in[0];
    const float* X       = (const float*)d_in[1];
    const int*   ei      = (const int*)  d_in[2];
    const int*   bidx    = (const int*)  d_in[3];
    const float* gr_wq   = (const float*)d_in[4];
    const float* gr_bq   = (const float*)d_in[5];
    const float* gr_aq_w = (const float*)d_in[6];
    const float* gr_aq_b = (const float*)d_in[7];
    const float* gr_ak_w = (const float*)d_in[8];
    // d_in[9] = gr_ak_b: per-(b,h) constant score shift, cancels in softmax
    const float* gr_av_w = (const float*)d_in[10];
    const float* gr_av_b = (const float*)d_in[11];
    const float* gr_ao_w = (const float*)d_in[12];
    const float* gr_ao_b = (const float*)d_in[13];
    const float* gr_ln_g = (const float*)d_in[14];
    const float* gr_ln_b = (const float*)d_in[15];
    const float* pf_wq   = (const float*)d_in[16];
    const float* pf_bq   = (const float*)d_in[17];
    const float* pf_wn   = (const float*)d_in[18];
    const float* pf_bn   = (const float*)d_in[19];
    const float* pf_a1_w = (const float*)d_in[20];
    const float* pf_a1_b = (const float*)d_in[21];
    const float* pf_a2_w = (const float*)d_in[22];
    const float* pf_a2_b = (const float*)d_in[23];
    const float* pf_ln_g = (const float*)d_in[24];
    const float* pf_ln_b = (const float*)d_in[25];
    const float* fu_gw   = (const float*)d_in[26];
    const float* fu_gb   = (const float*)d_in[27];
    const float* fu_pw   = (const float*)d_in[28];
    const float* fu_pb   = (const float*)d_in[29];
    const float* fu_ln_g = (const float*)d_in[30];
    const float* fu_ln_b = (const float*)d_in[31];
    float* out = (float*)d_out;

    float* G = addrf(g_buf);

    static cudaStream_t s1 = nullptr, s2 = nullptr;
    static cudaEvent_t evF = nullptr, evS = nullptr, evE = nullptr, evP = nullptr;
    static cudaEvent_t ev1 = nullptr, evQ = nullptr;
    if (!s1) {
        cudaStreamCreateWithFlags(&s1, cudaStreamNonBlocking);
        cudaStreamCreateWithFlags(&s2, cudaStreamNonBlocking);
        cudaEventCreateWithFlags(&evF, cudaEventDisableTiming);
        cudaEventCreateWithFlags(&evS, cudaEventDisableTiming);
        cudaEventCreateWithFlags(&evE, cudaEventDisableTiming);
        cudaEventCreateWithFlags(&evP, cudaEventDisableTiming);
        cudaEventCreateWithFlags(&ev1, cudaEventDisableTiming);
        cudaEventCreateWithFlags(&evQ, cudaEventDisableTiming);
    }

    // prep on capture stream, then fork edge scan
    k_prep<<<(TOTALF + 255) / 256, 256>>>();
    cudaEventRecord(evF, 0);
    cudaStreamWaitEvent(s2, evF, 0);
    k_edges<<<EE / 256, 256, 0, s2>>>(ei, bidx);
    cudaEventRecord(evE, s2);

    // main chain: projections -> scores
    {
        GPack p;
        p.d[0] = mkdesc(query, HH, gr_wq, HH, 0, gr_bq, G + O_QP,  HH, HH, HH, 0);
        p.d[1] = mkdesc(query, HH, pf_wq, HH, 0, pf_bq, G + O_QP2, HH, HH, HH, 0);
        k_gskm<<<dim3(24, 6, 2), 256>>>(p);
    }
    cudaEventRecord(ev1, 0);
    // qstats off the critical path (needs qp2 only; scores waits on evQ)
    cudaStreamWaitEvent(s1, ev1, 0);
    k_qstats<<<BB, 256, 0, s1>>>(pf_bn);
    cudaEventRecord(evQ, s1);
    {
        GPack p;
        p.d[0] = mkdesc(G + O_QP,  HH, gr_aq_w, HH, 0, gr_aq_b, G + O_Q, HH, HH, HH, 0);
        p.d[1] = mkdesc(G + O_QP2, HH, pf_wn,   HH, 1, nullptr, G + O_T, HH, HH, HH, 0);
        k_gskm<<<dim3(24, 6, 2), 256>>>(p);
    }
    {
        GPack p;
        for (int h = 0; h < NH; h++)
            p.d[h] = mkdesc(G + O_Q + h * DHH, HH, gr_ak_w + h * DHH, HH, 1, nullptr,
                            G + O_U + h * HH, NH * HH, HH, DHH, 0);
        k_gskm<<<dim3(24, 1, 8), 256>>>(p);
    }
    cudaStreamWaitEvent(0, evQ, 0);
    k_scores<<<512, 256>>>(X);
    cudaEventRecord(evS, 0);

    // s1: path branch (overlaps the attention rest)
    cudaStreamWaitEvent(s1, evS, 0);
    k_topnum<<<BB, 256, 0, s1>>>();
    k_recheck48<<<dim3(BB, 3, 6), 256, 0, s1>>>(X, pf_wn, pf_bn);
    cudaStreamWaitEvent(s1, evE, 0);
    k_pathfeat<<<BB, 256, 0, s1>>>(X, ei);
    {
        GPack p;
        p.d[0] = mkdesc(G + O_MEANP, HH, pf_a1_w, HH, 0, pf_a1_b, G + O_AGG1, HH, HH, HH, 0);
        k_gskm<<<dim3(24, 6, 1), 256, 0, s1>>>(p);
    }
    {
        GPack p;
        p.d[0] = mkdesc(G + O_AGG1, HH, pf_a2_w, HH, 0, pf_a2_b, G + O_AGG, HH, HH, HH, 1);
        k_gskm<<<dim3(24, 6, 1), 256, 0, s1>>>(p);
    }
    cudaEventRecord(evP, s1);

    // main: attention rest (smstats fused into k_scores)
    k_wsum<<<dim3(BB, 16), 192>>>(X);
    {
        GPack p;
        for (int h = 0; h < NH; h++)
            p.d[h] = mkdesc(G + O_WSUM + h * HH, NH * HH, gr_av_w + h * DHH, HH, 0,
                            gr_av_b + h * DHH, G + O_CTX + h * DHH, HH, DHH, HH, 0);
        k_gskm<<<dim3(3, 6, 8), 256>>>(p);
    }
    {
        GPack p;
        p.d[0] = mkdesc(G + O_CTX, HH, gr_ao_w, HH, 0, gr_ao_b, G + O_TMP1, HH, HH, HH, 0);
        p.d[1] = mkdesc(G + O_MEANX, HH, pf_wn, HH, 0, pf_bn, G + O_BMEAN, HH, HH, HH, 0);
        k_gskm<<<dim3(24, 6, 2), 256>>>(p);
    }
    k_ln<<<BB, 256>>>(G + O_TMP1, nullptr, 0, gr_ln_g, gr_ln_b, G + O_GRAPH);

    // join: path-LN needs AGG (s1) + BMEAN + cnt
    cudaStreamWaitEvent(0, evP, 0);
    k_ln<<<BB, 256>>>(G + O_AGG, G + O_BMEAN, 3, pf_ln_g, pf_ln_b, G + O_PATH);

    // fusion
    k_comb<<<BB * 3 * HH / 256, 256>>>(query);
    {
        GPack p;
        p.d[0] = mkdesc(G + O_COMB, 3 * HH, fu_gw, HH, 0, fu_gb, G + O_GATE,  HH, HH, 3 * HH, 0);
        p.d[1] = mkdesc(G + O_COMB, 3 * HH, fu_pw, HH, 0, fu_pb, G + O_FUSED, HH, HH, 3 * HH, 0);
        k_gskm<<<dim3(24, 18, 2), 256>>>(p);
    }
    k_ln<<<BB, 256>>>(G + O_FUSED, G + O_GATE, 2, fu_ln_g, fu_ln_b, out);
}

// round 17
// speedup vs baseline: 1.0759x; 1.0759x over previous
#include <cuda_runtime.h>
#include <math.h>
#include <stdint.h>

#define BB 32
#define NPB 2048
#define NN 65536
#define EE 1048576
#define HH 768
#define NH 8
#define DHH 96
#define KC 48
#define SCALE_V 0.10206207261596577f

// ---------------- unified fp32 scratch (zeroed once per launch) ----------------
#define O_QP     0
#define O_Q      24576
#define O_QP2    49152
#define O_T      73728
#define O_U      98304
#define O_CTX    294912
#define O_TMP1   319488
#define O_BMEAN  344064
#define O_AGG1   368640
#define O_AGG    393216
#define O_GATE   417792
#define O_FUSED  442368
#define O_WSUM   466944
#define O_MEANX  663552
#define O_MEANP  753664
#define O_PATH   802816
#define O_GRAPH  827392
#define O_COMB   851968
#define O_NUM    925952
#define O_QN     991488
#define O_C      991520
#define TOTALF   991552

__device__ float g_buf[TOTALF];
__device__ float g_scores[(size_t)NN*NH];
__device__ float g_se[BB*NH];
__device__ float g_csimp[BB*KC*3];
__device__ int   g_first_edge[NN];
__device__ int   g_cand[BB*KC];
__device__ int   g_cnt[BB];

// ---------------- prep: zero scratch, init first_edge ----------------
__global__ void k_prep() {
    int i = blockIdx.x * 256 + threadIdx.x;
    if (i < TOTALF) g_buf[i] = 0.f;
    if (i < NN) g_first_edge[i] = EE;
}

// ---------------- multi-descriptor split-K small GEMM ----------------
struct GDesc {
    const float* A; const float* B; const float* bias; float* C;
    int lda, ldb, ldc, transB, K, actA, nx, ky;
};
struct GPack { GDesc d[8]; };

__global__ void k_gskm(GPack p) {
    GDesc d = p.d[blockIdx.z];
    if ((int)blockIdx.x >= d.nx || (int)blockIdx.y >= d.ky) return;
    __shared__ float sA[32][129];
    __shared__ float sB[128][33];
    int t = threadIdx.x;
    int c0 = blockIdx.x * 32, k0 = blockIdx.y * 128;
    int kn = min(128, d.K - k0);
    for (int idx = t; idx < 32 * 128; idx += 256) {
        int m = idx >> 7, kk = idx & 127;
        float v = (kk < kn) ? d.A[(size_t)m * d.lda + k0 + kk] : 0.f;
        if (d.actA) v = fmaxf(v, 0.f);
        sA[m][kk] = v;
    }
    for (int idx = t; idx < 128 * 32; idx += 256) {
        int kk = idx >> 5, nn = idx & 31;
        float v = 0.f;
        if (kk < kn) v = d.transB ? d.B[(size_t)(c0 + nn) * d.ldb + k0 + kk]
                                  : d.B[(size_t)(k0 + kk) * d.ldb + c0 + nn];
        sB[kk][nn] = v;
    }
    __syncthreads();
    int g = t >> 5, tx = t & 31;
    float a0 = 0.f, a1 = 0.f, a2 = 0.f, a3 = 0.f;
#pragma unroll 8
    for (int kk = 0; kk < 128; kk++) {
        float bv = sB[kk][tx];
        a0 += sA[g][kk] * bv;
        a1 += sA[g + 8][kk] * bv;
        a2 += sA[g + 16][kk] * bv;
        a3 += sA[g + 24][kk] * bv;
    }
    float bb = (d.bias && blockIdx.y == 0) ? d.bias[c0 + tx] : 0.f;
    atomicAdd(&d.C[(size_t)(g     ) * d.ldc + c0 + tx], a0 + bb);
    atomicAdd(&d.C[(size_t)(g +  8) * d.ldc + c0 + tx], a1 + bb);
    atomicAdd(&d.C[(size_t)(g + 16) * d.ldc + c0 + tx], a2 + bb);
    atomicAdd(&d.C[(size_t)(g + 24) * d.ldc + c0 + tx], a3 + bb);
}

// ---------------- qp2 stats ----------------
__global__ void k_qstats(const float* __restrict__ bn) {
    int b = blockIdx.x, t = threadIdx.x;
    __shared__ float s1[256], s2[256];
    float a = 0.f, d = 0.f;
    for (int j = t; j < HH; j += 256) {
        float v = g_buf[O_QP2 + b * HH + j];
        a += v * v; d += v * bn[j];
    }
    s1[t] = a; s2[t] = d; __syncthreads();
    for (int o = 128; o > 0; o >>= 1) {
        if (t < o) { s1[t] += s1[t + o]; s2[t] += s2[t + o]; }
        __syncthreads();
    }
    if (t == 0) { g_buf[O_QN + b] = fmaxf(sqrtf(s1[0]), 1e-8f); g_buf[O_C + b] = s2[0]; }
}

// ---------------- per-node head scores + cosine numerator ----------------
__global__ void k_scores(const float* __restrict__ X) {
    __shared__ float sU[NH * HH];
    __shared__ float sT[HH];
    int b = blockIdx.x >> 4, sub = blockIdx.x & 15;
    for (int i = threadIdx.x; i < NH * HH; i += 256) sU[i] = g_buf[O_U + b * NH * HH + i];
    for (int i = threadIdx.x; i < HH; i += 256) sT[i] = g_buf[O_T + b * HH + i];
    __syncthreads();
    float cb = g_buf[O_C + b];
    int warp = threadIdx.x >> 5, lane = threadIdx.x & 31;
    int nodebase = b * NPB + sub * 128 + warp * 16;
    for (int w = 0; w < 16; w++) {
        int n = nodebase + w;
        const float* xr = X + (size_t)n * HH;
        float acc[9];
#pragma unroll
        for (int i = 0; i < 9; i++) acc[i] = 0.f;
#pragma unroll
        for (int cc = 0; cc < HH / 32; cc++) {
            int base = cc * 32 + lane;
            float xv = xr[base];
#pragma unroll
            for (int h = 0; h < 8; h++) acc[h] += xv * sU[h * HH + base];
            acc[8] += xv * sT[base];
        }
#pragma unroll
        for (int i = 0; i < 9; i++)
            for (int o = 16; o > 0; o >>= 1)
                acc[i] += __shfl_xor_sync(0xffffffffu, acc[i], o);
        if (lane == 0) {
#pragma unroll
            for (int h = 0; h < 8; h++) g_scores[(size_t)n * NH + h] = acc[h] * SCALE_V;
            g_buf[O_NUM + n] = acc[8] + cb;
        }
    }
}

// ---------------- softmax exp-sums per (b,h): sum-only, no max (scores bounded) ----------------
__global__ void k_smstats() {
    int b = blockIdx.x >> 3, h = blockIdx.x & 7;
    int t = threadIdx.x;
    __shared__ float sm[256];
    float s = 0.f;
    for (int i = t; i < NPB; i += 256)
        s += expf(g_scores[(size_t)(b * NPB + i) * NH + h]);
    sm[t] = s; __syncthreads();
    for (int o = 128; o > 0; o >>= 1) { if (t < o) sm[t] += sm[t + o]; __syncthreads(); }
    if (t == 0) g_se[b * NH + h] = sm[0];
}

// ---------------- attention-weighted sums + mean(x): float4 per thread ----------------
// grid (BB, 16): each CTA handles one 128-node segment; 192 threads x 4 cols = 768 cols.
__global__ void k_wsum(const float* __restrict__ X) {
    int b = blockIdx.x, seg = blockIdx.y;
    int t = threadIdx.x;                // 192
    __shared__ float sa[128][8];
    __shared__ float sse[8];
    if (t < 8) sse[t] = 1.f / g_se[b * NH + t];
    __syncthreads();
    int n0 = seg * 128;
    for (int idx = t; idx < 128 * 8; idx += 192) {
        int n = idx >> 3, h = idx & 7;
        sa[n][h] = expf(g_scores[(size_t)(b * NPB + n0 + n) * NH + h]) * sse[h];
    }
    __syncthreads();
    int col = t * 4;
    float acc[8][4];
#pragma unroll
    for (int h = 0; h < 8; h++)
#pragma unroll
        for (int j = 0; j < 4; j++) acc[h][j] = 0.f;
    float m0 = 0.f, m1 = 0.f, m2 = 0.f, m3 = 0.f;
#pragma unroll 4
    for (int nn = 0; nn < 128; nn++) {
        float4 xv = *(const float4*)(X + (size_t)(b * NPB + n0 + nn) * HH + col);
        m0 += xv.x; m1 += xv.y; m2 += xv.z; m3 += xv.w;
#pragma unroll
        for (int h = 0; h < 8; h++) {
            float a = sa[nn][h];
            acc[h][0] += a * xv.x;
            acc[h][1] += a * xv.y;
            acc[h][2] += a * xv.z;
            acc[h][3] += a * xv.w;
        }
    }
#pragma unroll
    for (int h = 0; h < 8; h++) {
        float* wp = &g_buf[O_WSUM + (size_t)(b * NH + h) * HH + col];
        atomicAdd(wp + 0, acc[h][0]);
        atomicAdd(wp + 1, acc[h][1]);
        atomicAdd(wp + 2, acc[h][2]);
        atomicAdd(wp + 3, acc[h][3]);
    }
    float inv = 1.f / (float)NPB;
    float* mp = &g_buf[O_MEANX + b * HH + col];
    atomicAdd(mp + 0, m0 * inv);
    atomicAdd(mp + 1, m1 * inv);
    atomicAdd(mp + 2, m2 * inv);
    atomicAdd(mp + 3, m3 * inv);
}

// ---------------- first intra-graph outgoing edge ----------------
__global__ void k_edges(const int* __restrict__ ei, const int* __restrict__ bidx) {
    int e = blockIdx.x * blockDim.x + threadIdx.x;
    if (e < EE) {
        int s = ei[e], d = ei[EE + e];
        if (bidx[s] == bidx[d]) atomicMin(&g_first_edge[s], e);
    }
}

// ---------------- top-48 shortlist by exact numerator (norms concentrate ±2.5%) ----------------
__global__ void k_topnum() {
    int b = blockIdx.x, t = threadIdx.x;
    __shared__ float sv[NPB];
    __shared__ float rv[256];
    __shared__ int ri[256];
    for (int i = t; i < NPB; i += 256)
        sv[i] = g_buf[O_NUM + b * NPB + i];
    __syncthreads();
    for (int k = 0; k < KC; k++) {
        float bv = -1e38f; int bi = 0x7fffffff;
        for (int i = t; i < NPB; i += 256) {
            float v = sv[i];
            if (v > bv || (v == bv && i < bi)) { bv = v; bi = i; }
        }
        rv[t] = bv; ri[t] = bi; __syncthreads();
        for (int o = 128; o > 0; o >>= 1) {
            if (t < o) {
                if (rv[t + o] > rv[t] || (rv[t + o] == rv[t] && ri[t + o] < ri[t])) {
                    rv[t] = rv[t + o]; ri[t] = ri[t + o];
                }
            }
            __syncthreads();
        }
        if (t == 0) { g_cand[b * KC + k] = b * NPB + ri[0]; sv[ri[0]] = -1e38f; }
        __syncthreads();
    }
}

// ---------------- exact fp32 norm partials for the 48 candidates ----------------
// grid (32, 3, 6): batch x column-third x candidate-group-of-8. Deterministic.
__global__ void k_recheck48(const float* __restrict__ X, const float* __restrict__ W,
                            const float* __restrict__ bn)
{
    int b = blockIdx.x, third = blockIdx.y, grp = blockIdx.z;
    int t = threadIdx.x;
    int col = third * 256 + t;
    __shared__ float sx[8][HH];
    __shared__ float sr[256];
    for (int i = t; i < 8 * HH; i += 256) {
        int c = i / HH, k = i % HH;
        sx[c][k] = X[(size_t)g_cand[b * KC + grp * 8 + c] * HH + k];
    }
    __syncthreads();
    float v[8];
#pragma unroll
    for (int c = 0; c < 8; c++) v[c] = bn[col];
#pragma unroll 4
    for (int k = 0; k < HH; k++) {
        float w = W[(size_t)k * HH + col];
#pragma unroll
        for (int c = 0; c < 8; c++) v[c] += sx[c][k] * w;
    }
    for (int c = 0; c < 8; c++) {
        sr[t] = v[c] * v[c]; __syncthreads();
        for (int o = 128; o > 0; o >>= 1) {
            if (t < o) sr[t] += sr[t + o];
            __syncthreads();
        }
        if (t == 0) g_csimp[(b * KC + grp * 8 + c) * 3 + third] = sr[0];
        __syncthreads();
    }
}

// ---------------- exact top-3 over 48 candidates + path features ----------------
__global__ void k_pathfeat(const float* __restrict__ X, const int* __restrict__ ei) {
    int b = blockIdx.x, t = threadIdx.x;
    __shared__ int st[3], snb[3], sval[3];
    __shared__ int scnt;
    if (t == 0) {
        float v[KC]; int ix[KC]; bool used[KC];
        float qninv = 1.f / g_buf[O_QN + b];
        for (int j = 0; j < KC; j++) {
            int node = g_cand[b * KC + j];
            float nsq = g_csimp[(b * KC + j) * 3 + 0]
                      + g_csimp[(b * KC + j) * 3 + 1]
                      + g_csimp[(b * KC + j) * 3 + 2];
            float nrm = fmaxf(sqrtf(nsq), 1e-8f);
            v[j] = g_buf[O_NUM + node] * qninv / nrm;
            ix[j] = node;
            used[j] = false;
        }
        int c = 0;
        for (int k = 0; k < 3; k++) {
            int best = -1;
            for (int j = 0; j < KC; j++)
                if (!used[j] && (best < 0 || v[j] > v[best] ||
                                 (v[j] == v[best] && ix[j] < ix[best]))) best = j;
            used[best] = true;
            int node = ix[best];
            int fe = g_first_edge[node];
            int vl = (fe < EE) ? 1 : 0;
            int nbr = ei[EE + (vl ? fe : 0)];
            st[k] = node; snb[k] = nbr; sval[k] = vl; c += vl;
        }
        scnt = c; g_cnt[b] = c;
    }
    __syncthreads();
    float invc = 1.f / fmaxf((float)scnt, 1.f);
    for (int j = t; j < HH; j += 256) {
        float s = 0.f;
        for (int k = 0; k < 3; k++)
            if (sval[k])
                s += (X[(size_t)st[k] * HH + j] + X[(size_t)snb[k] * HH + j]) * 0.5f;
        g_buf[O_MEANP + b * HH + j] = s * invc;
    }
}

// ---------------- comb = [query, graph, path] ----------------
__global__ void k_comb(const float* __restrict__ query) {
    int i = blockIdx.x * 256 + threadIdx.x;
    int b = i / (3 * HH), j = i % (3 * HH);
    float v;
    if (j < HH)          v = query[b * HH + j];
    else if (j < 2 * HH) v = g_buf[O_GRAPH + b * HH + j - HH];
    else                 v = g_buf[O_PATH + b * HH + j - 2 * HH];
    g_buf[O_COMB + i] = v;
}

// ---------------- layernorm; mode 2: in *= sigmoid(in2); mode 3: select in/in2 by g_cnt ----------------
__global__ void k_ln(const float* __restrict__ in, const float* __restrict__ in2, int mode,
                     const float* __restrict__ gg, const float* __restrict__ bb,
                     float* __restrict__ out)
{
    int b = blockIdx.x, t = threadIdx.x;
    __shared__ float sx[HH];
    __shared__ float red[256];
    float s = 0.f;
    for (int j = t; j < HH; j += 256) {
        float v = in[b * HH + j];
        if (mode == 2) v *= 1.f / (1.f + expf(-in2[b * HH + j]));
        else if (mode == 3 && g_cnt[b] <= 0) v = in2[b * HH + j];
        sx[j] = v; s += v;
    }
    red[t] = s; __syncthreads();
    for (int o = 128; o > 0; o >>= 1) { if (t < o) red[t] += red[t + o]; __syncthreads(); }
    float m = red[0] * (1.f / HH); __syncthreads();
    float vs = 0.f;
    for (int j = t; j < HH; j += 256) { float d = sx[j] - m; vs += d * d; }
    red[t] = vs; __syncthreads();
    for (int o = 128; o > 0; o >>= 1) { if (t < o) red[t] += red[t + o]; __syncthreads(); }
    float inv = rsqrtf(red[0] * (1.f / HH) + 1e-5f);
    for (int j = t; j < HH; j += 256)
        out[b * HH + j] = (sx[j] - m) * inv * gg[j] + bb[j];
}

// ---------------- host ----------------
static float* addrf(const void* sym) {
    void* p = nullptr;
    cudaGetSymbolAddress(&p, sym);
    return (float*)p;
}

static GDesc mkdesc(const float* A, int lda, const float* B, int ldb, int transB,
                    const float* bias, float* C, int ldc, int Ncols, int K, int actA) {
    GDesc d;
    d.A = A; d.B = B; d.bias = bias; d.C = C;
    d.lda = lda; d.ldb = ldb; d.ldc = ldc; d.transB = transB;
    d.K = K; d.actA = actA;
    d.nx = (Ncols + 31) / 32; d.ky = (K + 127) / 128;
    return d;
}

extern "C" void kernel_launch(void* const* d_in, const int* in_sizes, int n_in,
                              void* d_out, int out_size)
{
    const float* query   = (const float*)d_in[0];
    const float* X       = (const float*)d_in[1];
    const int*   ei      = (const int*)  d_in[2];
    const int*   bidx    = (const int*)  d_in[3];
    const float* gr_wq   = (const float*)d_in[4];
    const float* gr_bq   = (const float*)d_in[5];
    const float* gr_aq_w = (const float*)d_in[6];
    const float* gr_aq_b = (const float*)d_in[7];
    const float* gr_ak_w = (const float*)d_in[8];
    // d_in[9] = gr_ak_b: per-(b,h) constant score shift, cancels in softmax
    const float* gr_av_w = (const float*)d_in[10];
    const float* gr_av_b = (const float*)d_in[11];
    const float* gr_ao_w = (const float*)d_in[12];
    const float* gr_ao_b = (const float*)d_in[13];
    const float* gr_ln_g = (const float*)d_in[14];
    const float* gr_ln_b = (const float*)d_in[15];
    const float* pf_wq   = (const float*)d_in[16];
    const float* pf_bq   = (const float*)d_in[17];
    const float* pf_wn   = (const float*)d_in[18];
    const float* pf_bn   = (const float*)d_in[19];
    const float* pf_a1_w = (const float*)d_in[20];
    const float* pf_a1_b = (const float*)d_in[21];
    const float* pf_a2_w = (const float*)d_in[22];
    const float* pf_a2_b = (const float*)d_in[23];
    const float* pf_ln_g = (const float*)d_in[24];
    const float* pf_ln_b = (const float*)d_in[25];
    const float* fu_gw   = (const float*)d_in[26];
    const float* fu_gb   = (const float*)d_in[27];
    const float* fu_pw   = (const float*)d_in[28];
    const float* fu_pb   = (const float*)d_in[29];
    const float* fu_ln_g = (const float*)d_in[30];
    const float* fu_ln_b = (const float*)d_in[31];
    float* out = (float*)d_out;

    float* G = addrf(g_buf);

    static cudaStream_t s1 = nullptr, s2 = nullptr;
    static cudaEvent_t evF = nullptr, evS = nullptr, evE = nullptr, evP = nullptr;
    if (!s1) {
        cudaStreamCreateWithFlags(&s1, cudaStreamNonBlocking);
        cudaStreamCreateWithFlags(&s2, cudaStreamNonBlocking);
        cudaEventCreateWithFlags(&evF, cudaEventDisableTiming);
        cudaEventCreateWithFlags(&evS, cudaEventDisableTiming);
        cudaEventCreateWithFlags(&evE, cudaEventDisableTiming);
        cudaEventCreateWithFlags(&evP, cudaEventDisableTiming);
    }

    // prep on capture stream, then fork edge scan
    k_prep<<<(TOTALF + 255) / 256, 256>>>();
    cudaEventRecord(evF, 0);
    cudaStreamWaitEvent(s2, evF, 0);
    k_edges<<<EE / 256, 256, 0, s2>>>(ei, bidx);
    cudaEventRecord(evE, s2);

    // main chain: projections -> scores
    {
        GPack p;
        p.d[0] = mkdesc(query, HH, gr_wq, HH, 0, gr_bq, G + O_QP,  HH, HH, HH, 0);
        p.d[1] = mkdesc(query, HH, pf_wq, HH, 0, pf_bq, G + O_QP2, HH, HH, HH, 0);
        k_gskm<<<dim3(24, 6, 2), 256>>>(p);
    }
    k_qstats<<<BB, 256>>>(pf_bn);
    {
        GPack p;
        p.d[0] = mkdesc(G + O_QP,  HH, gr_aq_w, HH, 0, gr_aq_b, G + O_Q, HH, HH, HH, 0);
        p.d[1] = mkdesc(G + O_QP2, HH, pf_wn,   HH, 1, nullptr, G + O_T, HH, HH, HH, 0);
        k_gskm<<<dim3(24, 6, 2), 256>>>(p);
    }
    {
        GPack p;
        for (int h = 0; h < NH; h++)
            p.d[h] = mkdesc(G + O_Q + h * DHH, HH, gr_ak_w + h * DHH, HH, 1, nullptr,
                            G + O_U + h * HH, NH * HH, HH, DHH, 0);
        k_gskm<<<dim3(24, 1, 8), 256>>>(p);
    }
    k_scores<<<512, 256>>>(X);
    cudaEventRecord(evS, 0);

    // s1: path branch (overlaps the attention rest)
    cudaStreamWaitEvent(s1, evS, 0);
    k_topnum<<<BB, 256, 0, s1>>>();
    k_recheck48<<<dim3(BB, 3, 6), 256, 0, s1>>>(X, pf_wn, pf_bn);
    cudaStreamWaitEvent(s1, evE, 0);
    k_pathfeat<<<BB, 256, 0, s1>>>(X, ei);
    {
        GPack p;
        p.d[0] = mkdesc(G + O_MEANP, HH, pf_a1_w, HH, 0, pf_a1_b, G + O_AGG1, HH, HH, HH, 0);
        k_gskm<<<dim3(24, 6, 1), 256, 0, s1>>>(p);
    }
    {
        GPack p;
        p.d[0] = mkdesc(G + O_AGG1, HH, pf_a2_w, HH, 0, pf_a2_b, G + O_AGG, HH, HH, HH, 1);
        k_gskm<<<dim3(24, 6, 1), 256, 0, s1>>>(p);
    }
    cudaEventRecord(evP, s1);

    // main: attention rest
    k_smstats<<<BB * NH, 256>>>();
    k_wsum<<<dim3(BB, 16), 192>>>(X);
    {
        GPack p;
        for (int h = 0; h < NH; h++)
            p.d[h] = mkdesc(G + O_WSUM + h * HH, NH * HH, gr_av_w + h * DHH, HH, 0,
                            gr_av_b + h * DHH, G + O_CTX + h * DHH, HH, DHH, HH, 0);
        k_gskm<<<dim3(3, 6, 8), 256>>>(p);
    }
    {
        GPack p;
        p.d[0] = mkdesc(G + O_CTX, HH, gr_ao_w, HH, 0, gr_ao_b, G + O_TMP1, HH, HH, HH, 0);
        p.d[1] = mkdesc(G + O_MEANX, HH, pf_wn, HH, 0, pf_bn, G + O_BMEAN, HH, HH, HH, 0);
        k_gskm<<<dim3(24, 6, 2), 256>>>(p);
    }
    k_ln<<<BB, 256>>>(G + O_TMP1, nullptr, 0, gr_ln_g, gr_ln_b, G + O_GRAPH);

    // join: path-LN needs AGG (s1) + BMEAN + cnt
    cudaStreamWaitEvent(0, evP, 0);
    k_ln<<<BB, 256>>>(G + O_AGG, G + O_BMEAN, 3, pf_ln_g, pf_ln_b, G + O_PATH);

    // fusion
    k_comb<<<BB * 3 * HH / 256, 256>>>(query);
    {
        GPack p;
        p.d[0] = mkdesc(G + O_COMB, 3 * HH, fu_gw, HH, 0, fu_gb, G + O_GATE,  HH, HH, 3 * HH, 0);
        p.d[1] = mkdesc(G + O_COMB, 3 * HH, fu_pw, HH, 0, fu_pb, G + O_FUSED, HH, HH, 3 * HH, 0);
        k_gskm<<<dim3(24, 18, 2), 256>>>(p);
    }
    k_ln<<<BB, 256>>>(G + O_FUSED, G + O_GATE, 2, fu_ln_g, fu_ln_b, out);
}